// round 4
// baseline (speedup 1.0000x reference)
#include <cuda_runtime.h>

typedef unsigned long long ull;

#define T_STEPS 1024
#define BATCH   64
#define DIN     256
#define H0      512
#define H1      256
#define NCTA    128
#define NTHR    256
#define VSTR    66           // padded smem stride (floats) for v chunk rows

// K layout of the shared per-step input vector v (length 1024):
//   [0,256)    = x_t            (layer0 only)
//   [256,768)  = h0_{t-1}       (layer0 + layer1)
//   [768,1024) = h1_{t-2}       (layer1 only)
// Layer0 GEMM K-range: [0,768).  Layer1 GEMM K-range: [256,1024) (local k1 = k-256).

// ---- persistent device state (zero-init; no allocations) ----
__device__ float g_h0[2][H0 * BATCH];          // [parity][unit*64 + b]
__device__ float g_h1[2][H1 * BATCH];
__device__ unsigned g_count = 0;               // barrier count (reset each release)
__device__ volatile unsigned g_phase = 0;      // barrier phase (monotone across replays)

__device__ __forceinline__ ull ffma2(ull a, ull b, ull c) {
    ull d;
    asm("fma.rn.f32x2 %0, %1, %2, %3;" : "=l"(d) : "l"(a), "l"(b), "l"(c));
    return d;
}
__device__ __forceinline__ ull dup32(float w) {
    unsigned u = __float_as_uint(w);
    return ((ull)u << 32) | (ull)u;
}
__device__ __forceinline__ float sigmf(float x) {
    return 1.0f / (1.0f + __expf(-x));
}

// Sense-reversing grid barrier. Safe: 221KB smem -> 1 CTA/SM, 128 CTAs <= 148 SMs,
// all CTAs co-resident in wave 1. Count self-resets -> consistent across graph replays.
__device__ __forceinline__ void grid_barrier() {
    __syncthreads();
    if (threadIdx.x == 0) {
        __threadfence();                           // publish g_h0/g_h1/out writes
        unsigned ph = g_phase;
        if (atomicAdd(&g_count, 1u) == (unsigned)(gridDim.x - 1)) {
            atomicExch(&g_count, 0u);
            __threadfence();
            g_phase = ph + 1u;                     // release
        } else {
            while (g_phase == ph) { __nanosleep(64); }
            __threadfence();                       // acquire
        }
    }
    __syncthreads();
}

template<bool L0, bool L1>
__device__ __forceinline__ void gemm_chunk(const float* __restrict__ vb,
                                           const ull* __restrict__ w0p,
                                           const ull* __restrict__ w1p,
                                           ull& a0, ull& a0b, ull& a1,
                                           int p, int cc) {
    const float* vp_ptr = vb + 2 * p;
    const ull* w0 = w0p + cc;
    const ull* w1 = w1p + cc;
#pragma unroll 8
    for (int kk = 0; kk < 256; kk++) {
        ull vp = *(const ull*)vp_ptr;              // batches (2p, 2p+1) packed
        vp_ptr += VSTR;
        if (L0) {
            a0  = ffma2(w0[0], vp, a0);            // smem col cc
            a0b = ffma2(w0[8], vp, a0b);           // smem col cc+8
            w0 += 16;
        }
        if (L1) {
            a1 = ffma2(w1[0], vp, a1);             // smem col cc
            w1 += 8;
        }
    }
}

__global__ void __launch_bounds__(NTHR, 1)
lstm2_kernel(const float* __restrict__ x,
             const float* __restrict__ Wih0, const float* __restrict__ bih0,
             const float* __restrict__ Whh0, const float* __restrict__ bhh0,
             const float* __restrict__ Wih1, const float* __restrict__ bih1,
             const float* __restrict__ Whh1, const float* __restrict__ bhh1,
             float* __restrict__ out)
{
    extern __shared__ char smraw[];
    ull*   w0d    = reinterpret_cast<ull*>(smraw);        // [768][16] lane-duplicated
    ull*   w1d    = w0d + 768 * 16;                       // [768][8]
    float* b0s    = reinterpret_cast<float*>(w1d + 768 * 8);  // [16]
    float* b1s    = b0s + 16;                             // [8]
    float* gates0 = b1s + 8;                              // [16][64]
    float* gates1 = gates0 + 16 * BATCH;                  // [8][64]
    float* vbuf   = gates1 + 8 * BATCH;                   // [256][VSTR]

    const int tid = threadIdx.x;
    const int cta = blockIdx.x;
    const int p   = tid & 31;        // batch-pair index: batches (2p, 2p+1)
    const int cc  = tid >> 5;        // 0..7

    // ---- one-time weight staging into smem (lane-duplicated for f32x2) ----
    // Layer0: smem col c (0..15): gate g=c>>2, unit u=c&3 -> global col j = g*512 + cta*4 + u
    for (int idx = tid; idx < 768 * 16; idx += NTHR) {
        int k = idx >> 4, c = idx & 15;
        int j = (c >> 2) * 512 + cta * 4 + (c & 3);
        float w = (k < 256) ? Wih0[(size_t)k * 2048 + j]
                            : Whh0[(size_t)(k - 256) * 2048 + j];
        w0d[idx] = dup32(w);
    }
    // Layer1: smem col c (0..7): gate g=c>>1, unit u=c&1 -> j = g*256 + cta*2 + u
    // local k1: [0,512) = h0 input (Wih1), [512,768) = h1 recurrent (Whh1)
    for (int idx = tid; idx < 768 * 8; idx += NTHR) {
        int k = idx >> 3, c = idx & 7;
        int j = (c >> 1) * 256 + cta * 2 + (c & 1);
        float w = (k < 512) ? Wih1[(size_t)k * 1024 + j]
                            : Whh1[(size_t)(k - 512) * 1024 + j];
        w1d[idx] = dup32(w);
    }
    if (tid < 16) {
        int j = (tid >> 2) * 512 + cta * 4 + (tid & 3);
        b0s[tid] = bih0[j] + bhh0[j];
    }
    if (tid < 8) {
        int j = (tid >> 1) * 256 + cta * 2 + (tid & 1);
        b1s[tid] = bih1[j] + bhh1[j];
    }

    // thread-local cell states
    // L0 activation ownership: unit u = tid>>6 (0..3), batch b = tid&63
    // L1 activation ownership (tid<128): unit u1 = tid>>6 (0..1), batch b = tid&63
    float c0 = 0.0f;
    float c1 = 0.0f;
    const int act_u = tid >> 6;
    const int act_b = tid & 63;

    __syncthreads();

    // ---- main recurrence: iteration t computes layer0 step t and layer1 step t-1 ----
    for (int t = 0; t <= T_STEPS; t++) {
        ull a0  = dup32(b0s[cc]);
        ull a0b = dup32(b0s[cc + 8]);
        ull a1  = dup32(b1s[cc]);

        const bool hasL0 = (t < T_STEPS);
        const bool hasL1 = (t >= 1);

#pragma unroll 1
        for (int ci = 0; ci < 4; ci++) {           // 4 mega-chunks of K=256
            __syncthreads();                        // vbuf free (prev chunk consumed)
            // ---- stage v chunk into smem ----
            if (ci == 0) {
                if (hasL0) {
                    // x_t : coalesced over k (float4), scattered STS over 4 rows
                    const float* xb = x + (size_t)t * DIN;
#pragma unroll
                    for (int i = 0; i < 16; i++) {
                        int f  = tid + i * NTHR;
                        int kg = f & 63;            // k4 = kg*4
                        int b  = f >> 6;
                        float4 v4 = *reinterpret_cast<const float4*>(
                            xb + (size_t)b * (T_STEPS * DIN) + kg * 4);
                        float* dst = vbuf + (kg * 4) * VSTR + b;
                        dst[0]        = v4.x;
                        dst[VSTR]     = v4.y;
                        dst[2 * VSTR] = v4.z;
                        dst[3 * VSTR] = v4.w;
                    }
                } // else: layer0 inactive this iter; chunk never read
            } else if (ci < 3) {
                // h0_{t-1}: contiguous [k][b] copy, fully coalesced
                const float* src = g_h0[(t - 1) & 1] + (ci - 1) * 256 * BATCH;
                if (t >= 1) {
#pragma unroll
                    for (int i = 0; i < 64; i++) {
                        int f = tid + i * NTHR;
                        vbuf[(f >> 6) * VSTR + (f & 63)] = src[f];
                    }
                } else {
#pragma unroll
                    for (int i = 0; i < 64; i++) {
                        int f = tid + i * NTHR;
                        vbuf[(f >> 6) * VSTR + (f & 63)] = 0.0f;
                    }
                }
            } else {
                // h1_{t-2}: written at iter t-1 into g_h1[(t-2)&1] == g_h1[t&1]
                const float* src = g_h1[t & 1];
                if (t >= 2) {
#pragma unroll
                    for (int i = 0; i < 64; i++) {
                        int f = tid + i * NTHR;
                        vbuf[(f >> 6) * VSTR + (f & 63)] = src[f];
                    }
                } else {
#pragma unroll
                    for (int i = 0; i < 64; i++) {
                        int f = tid + i * NTHR;
                        vbuf[(f >> 6) * VSTR + (f & 63)] = 0.0f;
                    }
                }
            }
            __syncthreads();

            // ---- GEMM on this chunk ----
            const int kbase = ci * 256;
            const ull* w0p = w0d + kbase * 16;
            const ull* w1p = w1d + (kbase - 256) * 8;   // only deref'd when ci>=1
            const bool d0 = (ci < 3) && hasL0;
            const bool d1 = (ci >= 1) && hasL1;
            if (d0 && d1)      gemm_chunk<true,  true >(vbuf, w0p, w1p, a0, a0b, a1, p, cc);
            else if (d0)       gemm_chunk<true,  false>(vbuf, w0p, w1p, a0, a0b, a1, p, cc);
            else if (d1)       gemm_chunk<false, true >(vbuf, w0p, w1p, a0, a0b, a1, p, cc);
        }

        // ---- publish gate accumulators (batch-pair packed -> [col][b]) ----
        *reinterpret_cast<ull*>(&gates0[cc * BATCH + 2 * p])       = a0;
        *reinterpret_cast<ull*>(&gates0[(cc + 8) * BATCH + 2 * p]) = a0b;
        *reinterpret_cast<ull*>(&gates1[cc * BATCH + 2 * p])       = a1;
        __syncthreads();

        // ---- activations ----
        if (hasL0) {
            // cols: i=u, f=4+u, g=8+u, o=12+u
            float gi = gates0[(act_u)      * BATCH + act_b];
            float gf = gates0[(4 + act_u)  * BATCH + act_b];
            float gg = gates0[(8 + act_u)  * BATCH + act_b];
            float go = gates0[(12 + act_u) * BATCH + act_b];
            c0 = sigmf(gf) * c0 + sigmf(gi) * tanhf(gg);
            float h = sigmf(go) * tanhf(c0);
            g_h0[t & 1][(cta * 4 + act_u) * BATCH + act_b] = h;
        }
        if (hasL1 && tid < 128) {
            int u1 = act_u;                        // 0..1
            float gi = gates1[(u1)     * BATCH + act_b];
            float gf = gates1[(2 + u1) * BATCH + act_b];
            float gg = gates1[(4 + u1) * BATCH + act_b];
            float go = gates1[(6 + u1) * BATCH + act_b];
            c1 = sigmf(gf) * c1 + sigmf(gi) * tanhf(gg);
            float h = sigmf(go) * tanhf(c1);
            int s = t - 1;                         // layer1 time index
            g_h1[s & 1][(cta * 2 + u1) * BATCH + act_b] = h;
            out[((size_t)act_b * T_STEPS + s) * H1 + cta * 2 + u1] = h;
        }

        if (t < T_STEPS) grid_barrier();           // all 1024 barriers uniform per launch
    }
}

#define SMEM_BYTES (768*16*8 + 768*8*8 + 16*4 + 8*4 + 16*64*4 + 8*64*4 + 256*VSTR*4)

extern "C" void kernel_launch(void* const* d_in, const int* in_sizes, int n_in,
                              void* d_out, int out_size) {
    (void)in_sizes; (void)n_in; (void)out_size;
    cudaFuncSetAttribute(lstm2_kernel,
                         cudaFuncAttributeMaxDynamicSharedMemorySize, SMEM_BYTES);
    lstm2_kernel<<<NCTA, NTHR, SMEM_BYTES>>>(
        (const float*)d_in[0],
        (const float*)d_in[1], (const float*)d_in[2],
        (const float*)d_in[3], (const float*)d_in[4],
        (const float*)d_in[5], (const float*)d_in[6],
        (const float*)d_in[7], (const float*)d_in[8],
        (float*)d_out);
}

// round 5
// speedup vs baseline: 1.2641x; 1.2641x over previous
#include <cuda_runtime.h>

typedef unsigned long long ull;

#define T_STEPS 1024
#define BATCH   64
#define DIN     256
#define H0      512
#define H1      256
#define NCTA    128
#define NTHR    512
#define VSTR    66

// K layout of per-step input vector v (length 1024), staged in 4 chunks of 256:
//   [0,256)    = x_t        (layer0 only)
//   [256,768)  = h0_{t-1}   (layer0 k[256,768) + layer1 k1[0,512))
//   [768,1024) = h1_{t-2}   (layer1 k1[512,768))
// Thread tiling: p = pair (batches 2p,2p+1), cl in {0,1}, ks in {0..7}
//   L0: cl owns units {2cl,2cl+1} x 4 gates = 8 cols; k in [96ks, 96ks+96)
//   L1: cl owns unit cl x 4 gates = 4 cols;         k in [256+96ks, 352+96ks)
// ks-partials reduced through smem once per step.

__device__ float g_xT[T_STEPS * DIN * BATCH];   // x transposed to [t][k][b]
__device__ float g_h0[2][H0 * BATCH];
__device__ float g_h1[2][H1 * BATCH];
__device__ unsigned g_count = 0;
__device__ volatile unsigned g_phase = 0;

__device__ __forceinline__ ull ffma2(ull a, ull b, ull c) {
    ull d;
    asm("fma.rn.f32x2 %0, %1, %2, %3;" : "=l"(d) : "l"(a), "l"(b), "l"(c));
    return d;
}
__device__ __forceinline__ ull addf2(ull a, ull b) {
    ull d;
    asm("add.rn.f32x2 %0, %1, %2;" : "=l"(d) : "l"(a), "l"(b));
    return d;
}
__device__ __forceinline__ ull dup32(float w) {
    unsigned u = __float_as_uint(w);
    return ((ull)u << 32) | (ull)u;
}
__device__ __forceinline__ float sigmf(float x) {
    return 1.0f / (1.0f + __expf(-x));
}
__device__ __forceinline__ int imax(int a, int b) { return a > b ? a : b; }
__device__ __forceinline__ int imin(int a, int b) { return a < b ? a : b; }

// Sense-reversing grid barrier. Safe: 216KB smem -> 1 CTA/SM, 128 CTAs <= 148 SMs,
// all co-resident in wave 1. Count self-resets -> consistent across graph replays.
__device__ __forceinline__ void grid_barrier() {
    __syncthreads();
    if (threadIdx.x == 0) {
        __threadfence();
        unsigned ph = g_phase;
        if (atomicAdd(&g_count, 1u) == (unsigned)(gridDim.x - 1)) {
            atomicExch(&g_count, 0u);
            __threadfence();
            g_phase = ph + 1u;
        } else {
            while (g_phase == ph) { __nanosleep(32); }
            __threadfence();
        }
    }
    __syncthreads();
}

__global__ void __launch_bounds__(NTHR, 1)
lstm2_kernel(const float* __restrict__ x,
             const float* __restrict__ Wih0, const float* __restrict__ bih0,
             const float* __restrict__ Whh0, const float* __restrict__ bhh0,
             const float* __restrict__ Wih1, const float* __restrict__ bih1,
             const float* __restrict__ Whh1, const float* __restrict__ bhh1,
             float* __restrict__ out)
{
    extern __shared__ char smraw[];
    ull*   w0d    = reinterpret_cast<ull*>(smraw);            // [768][16] lane-dup
    ull*   w1d    = w0d + 768 * 16;                           // [768][8]
    float* bcol   = reinterpret_cast<float*>(w1d + 768 * 8);  // [24] bias in c-order
    float* gates0 = bcol + 24;                                // [16][64]
    float* gates1 = gates0 + 16 * BATCH;                      // [8][64]
    float* fbase  = gates1 + 8 * BATCH;                       // union area (16B aligned)
    float* vbuf   = fbase;                                    // [256][VSTR]
    ull*   red    = reinterpret_cast<ull*>(fbase);            // [24][8][32] partials

    const int tid = threadIdx.x;
    const int cta = blockIdx.x;
    const int p   = tid & 31;            // batch pair (2p, 2p+1)
    const int wrp = tid >> 5;            // 0..15
    const int cl  = wrp & 1;
    const int ks  = wrp >> 1;            // 0..7
    const int L0lo = 96 * ks, L0hi = L0lo + 96;
    const int L1lo = 256 + 96 * ks, L1hi = L1lo + 96;

    // ---- one-time: transpose x (B,T,K) -> g_xT (T,K,B); coalesced writes ----
    {
        const size_t total = (size_t)BATCH * T_STEPS * (DIN / 4);  // float4 groups
        for (size_t idx = (size_t)cta * NTHR + tid; idx < total; idx += (size_t)NCTA * NTHR) {
            int b  = (int)(idx & 63);
            size_t r = idx >> 6;
            int kg = (int)(r & 63);
            int t  = (int)(r >> 6);
            float4 v4 = *reinterpret_cast<const float4*>(
                x + ((size_t)b * T_STEPS + t) * DIN + kg * 4);
            float* dst = g_xT + ((size_t)t * DIN + kg * 4) * BATCH + b;
            dst[0 * BATCH] = v4.x;
            dst[1 * BATCH] = v4.y;
            dst[2 * BATCH] = v4.z;
            dst[3 * BATCH] = v4.w;
        }
    }

    // ---- one-time: stage weights into smem (lane-duplicated for f32x2) ----
    // L0 smem col c = cl_*8 + g*2 + u'  ->  unit u = 2*cl_ + u', global j = g*512 + cta*4 + u
    for (int idx = tid; idx < 768 * 16; idx += NTHR) {
        int k = idx >> 4, c = idx & 15;
        int cl_ = c >> 3, g = (c >> 1) & 3, up = c & 1;
        int j = g * 512 + cta * 4 + 2 * cl_ + up;
        float w = (k < 256) ? Wih0[(size_t)k * 2048 + j]
                            : Whh0[(size_t)(k - 256) * 2048 + j];
        w0d[idx] = dup32(w);
    }
    // L1 smem col c = cl_*4 + g -> unit u1 = cl_, global j = g*256 + cta*2 + cl_
    for (int idx = tid; idx < 768 * 8; idx += NTHR) {
        int k = idx >> 3, c = idx & 7;
        int cl_ = c >> 2, g = c & 3;
        int j = g * 256 + cta * 2 + cl_;
        float w = (k < 512) ? Wih1[(size_t)k * 1024 + j]
                            : Whh1[(size_t)(k - 512) * 1024 + j];
        w1d[idx] = dup32(w);
    }
    if (tid < 16) {
        int cl_ = tid >> 3, g = (tid >> 1) & 3, up = tid & 1;
        int j = g * 512 + cta * 4 + 2 * cl_ + up;
        bcol[tid] = bih0[j] + bhh0[j];
    } else if (tid < 24) {
        int c = tid - 16;
        int cl_ = c >> 2, g = c & 3;
        int j = g * 256 + cta * 2 + cl_;
        bcol[tid] = bih1[j] + bhh1[j];
    }

    float cst = 0.0f;   // c0 for tid<256 (unit tid>>6, batch tid&63); c1 for tid in [256,384)

    __syncthreads();
    grid_barrier();     // g_xT complete before anyone reads it

    // ---- main recurrence: iteration t = layer0 step t + layer1 step t-1 ----
    for (int t = 0; t <= T_STEPS; t++) {
        ull a0[8], a1[4];
#pragma unroll
        for (int j = 0; j < 8; j++) a0[j] = 0ull;
#pragma unroll
        for (int j = 0; j < 4; j++) a1[j] = 0ull;

        const bool hasL0 = (t < T_STEPS);
        const bool hasL1 = (t >= 1);

#pragma unroll 1
        for (int ci = 0; ci < 4; ci++) {
            __syncthreads();                 // union area free (prev reads done)
            // ---- stage 256-row v chunk into smem, [k][b], contiguous ----
            if (ci == 0) {
                if (hasL0) {
                    const float* src = g_xT + (size_t)t * DIN * BATCH;
#pragma unroll
                    for (int i = 0; i < 32; i++) {
                        int f = tid + i * NTHR;
                        vbuf[(f >> 6) * VSTR + (f & 63)] = src[f];
                    }
                }
            } else if (ci < 3) {
                if (t >= 1) {
                    const float* src = g_h0[(t - 1) & 1] + (ci - 1) * 256 * BATCH;
#pragma unroll
                    for (int i = 0; i < 32; i++) {
                        int f = tid + i * NTHR;
                        vbuf[(f >> 6) * VSTR + (f & 63)] = src[f];
                    }
                } else {
#pragma unroll
                    for (int i = 0; i < 32; i++) {
                        int f = tid + i * NTHR;
                        vbuf[(f >> 6) * VSTR + (f & 63)] = 0.0f;
                    }
                }
            } else {
                if (t >= 2) {
                    const float* src = g_h1[t & 1];    // written at iter t-1 = step t-2
#pragma unroll
                    for (int i = 0; i < 32; i++) {
                        int f = tid + i * NTHR;
                        vbuf[(f >> 6) * VSTR + (f & 63)] = src[f];
                    }
                } else {
#pragma unroll
                    for (int i = 0; i < 32; i++) {
                        int f = tid + i * NTHR;
                        vbuf[(f >> 6) * VSTR + (f & 63)] = 0.0f;
                    }
                }
            }
            __syncthreads();

            const int cbase = ci << 8;
            // ---- L0 GEMM slice ----
            if (hasL0) {
                int lo = imax(L0lo, cbase), hi = imin(L0hi, cbase + 256);
                const ull* wp = w0d + lo * 16 + cl * 8;
                const float* vptr = vbuf + (lo - cbase) * VSTR + 2 * p;
#pragma unroll 4
                for (int k = lo; k < hi; k++) {
                    ull vp = *reinterpret_cast<const ull*>(vptr);
                    vptr += VSTR;
                    ulonglong2 wA = *reinterpret_cast<const ulonglong2*>(wp + 0);
                    ulonglong2 wB = *reinterpret_cast<const ulonglong2*>(wp + 2);
                    ulonglong2 wC = *reinterpret_cast<const ulonglong2*>(wp + 4);
                    ulonglong2 wD = *reinterpret_cast<const ulonglong2*>(wp + 6);
                    wp += 16;
                    a0[0] = ffma2(wA.x, vp, a0[0]);
                    a0[1] = ffma2(wA.y, vp, a0[1]);
                    a0[2] = ffma2(wB.x, vp, a0[2]);
                    a0[3] = ffma2(wB.y, vp, a0[3]);
                    a0[4] = ffma2(wC.x, vp, a0[4]);
                    a0[5] = ffma2(wC.y, vp, a0[5]);
                    a0[6] = ffma2(wD.x, vp, a0[6]);
                    a0[7] = ffma2(wD.y, vp, a0[7]);
                }
            }
            // ---- L1 GEMM slice ----
            if (hasL1) {
                int lo = imax(L1lo, cbase), hi = imin(L1hi, cbase + 256);
                const ull* wp = w1d + (lo - 256) * 8 + cl * 4;
                const float* vptr = vbuf + (lo - cbase) * VSTR + 2 * p;
#pragma unroll 4
                for (int k = lo; k < hi; k++) {
                    ull vp = *reinterpret_cast<const ull*>(vptr);
                    vptr += VSTR;
                    ulonglong2 wA = *reinterpret_cast<const ulonglong2*>(wp + 0);
                    ulonglong2 wB = *reinterpret_cast<const ulonglong2*>(wp + 2);
                    wp += 8;
                    a1[0] = ffma2(wA.x, vp, a1[0]);
                    a1[1] = ffma2(wA.y, vp, a1[1]);
                    a1[2] = ffma2(wB.x, vp, a1[2]);
                    a1[3] = ffma2(wB.y, vp, a1[3]);
                }
            }
        }

        __syncthreads();     // gemm reads of vbuf done -> red (aliased) writes safe
        // ---- dump ks-partials: red[c][ks][p] ----
#pragma unroll
        for (int j = 0; j < 8; j++)
            red[(((cl << 3) + j) * 8 + ks) * 32 + p] = a0[j];
#pragma unroll
        for (int j = 0; j < 4; j++)
            red[((16 + (cl << 2) + j) * 8 + ks) * 32 + p] = a1[j];
        __syncthreads();

        // ---- reduce 24 cols x 32 pairs over 8 ks-partials, add bias, scatter to gates ----
        for (int i = tid; i < 768; i += NTHR) {
            int c = i >> 5, pp = i & 31;
            const ull* r = red + (c * 8) * 32 + pp;
            ull s = dup32(bcol[c]);
#pragma unroll
            for (int q = 0; q < 8; q++) s = addf2(s, r[q * 32]);
            if (c < 16) {
                int cl_ = c >> 3, g = (c >> 1) & 3, up = c & 1;
                int u = 2 * cl_ + up;
                *reinterpret_cast<ull*>(&gates0[(g * 4 + u) * BATCH + 2 * pp]) = s;
            } else {
                int cc1 = c - 16, cl_ = cc1 >> 2, g = cc1 & 3;
                *reinterpret_cast<ull*>(&gates1[(g * 2 + cl_) * BATCH + 2 * pp]) = s;
            }
        }
        __syncthreads();

        // ---- activations (L0 and L1 on disjoint warps, parallel) ----
        if (hasL0 && tid < 256) {
            int u = tid >> 6, b = tid & 63;
            float gi = gates0[(u)      * BATCH + b];
            float gf = gates0[(4 + u)  * BATCH + b];
            float gg = gates0[(8 + u)  * BATCH + b];
            float go = gates0[(12 + u) * BATCH + b];
            cst = sigmf(gf) * cst + sigmf(gi) * tanhf(gg);
            g_h0[t & 1][(cta * 4 + u) * BATCH + b] = sigmf(go) * tanhf(cst);
        }
        if (hasL1 && tid >= 256 && tid < 384) {
            int u1 = (tid >> 6) & 1, b = tid & 63;
            float gi = gates1[(u1)     * BATCH + b];
            float gf = gates1[(2 + u1) * BATCH + b];
            float gg = gates1[(4 + u1) * BATCH + b];
            float go = gates1[(6 + u1) * BATCH + b];
            cst = sigmf(gf) * cst + sigmf(gi) * tanhf(gg);
            float h = sigmf(go) * tanhf(cst);
            int s = t - 1;
            g_h1[s & 1][(cta * 2 + u1) * BATCH + b] = h;
            out[((size_t)b * T_STEPS + s) * H1 + cta * 2 + u1] = h;
        }

        if (t < T_STEPS) grid_barrier();
    }
}

// smem: weights 147456 + floats (24+1024+512)*4 = 6240 + union max(vbuf 67584, red 49152)
#define SMEM_BYTES (147456 + 6240 + 67584)

extern "C" void kernel_launch(void* const* d_in, const int* in_sizes, int n_in,
                              void* d_out, int out_size) {
    (void)in_sizes; (void)n_in; (void)out_size;
    cudaFuncSetAttribute(lstm2_kernel,
                         cudaFuncAttributeMaxDynamicSharedMemorySize, SMEM_BYTES);
    lstm2_kernel<<<NCTA, NTHR, SMEM_BYTES>>>(
        (const float*)d_in[0],
        (const float*)d_in[1], (const float*)d_in[2],
        (const float*)d_in[3], (const float*)d_in[4],
        (const float*)d_in[5], (const float*)d_in[6],
        (const float*)d_in[7], (const float*)d_in[8],
        (float*)d_out);
}

// round 6
// speedup vs baseline: 1.4663x; 1.1599x over previous
#include <cuda_runtime.h>

typedef unsigned long long ull;

#define T_STEPS 1024
#define BATCH   64
#define DIN     256
#define H0      512
#define H1      256
#define NCTA    128
#define NTHR    512

// Per-step input vector v (K=1024), staged in 4 chunks of 256 rows x 64 batch:
//   [0,256)    = x_t        (layer0 only)
//   [256,768)  = h0_{t-1}   (layer0 + layer1)
//   [768,1024) = h1_{t-2}   (layer1 only)
// Thread tile: q = tid&15 (batches 4q..4q+3), cl = (tid>>4)&1, ks = tid>>5 (0..15)
//   L0: cl owns 8 gate-cols, k in [48ks, 48ks+48)
//   L1: cl owns 4 gate-cols, local k1 in [48ks, 48ks+48)  (global k = 256+k1)
// 16 ks-partials reduced in two waves through smem (aliased over vbuf).

__device__ float g_xT[T_STEPS * DIN * BATCH];   // x transposed to [t][k][b]
__device__ float g_h0[2][H0 * BATCH];
__device__ float g_h1[2][H1 * BATCH];
__device__ unsigned g_count = 0;
__device__ volatile unsigned g_phase = 0;

__device__ __forceinline__ ull ffma2(ull a, ull b, ull c) {
    ull d;
    asm("fma.rn.f32x2 %0, %1, %2, %3;" : "=l"(d) : "l"(a), "l"(b), "l"(c));
    return d;
}
__device__ __forceinline__ ull addf2(ull a, ull b) {
    ull d;
    asm("add.rn.f32x2 %0, %1, %2;" : "=l"(d) : "l"(a), "l"(b));
    return d;
}
__device__ __forceinline__ ull dup32(float w) {
    unsigned u = __float_as_uint(w);
    return ((ull)u << 32) | (ull)u;
}
__device__ __forceinline__ float sigmf(float x) {
    return 1.0f / (1.0f + __expf(-x));
}
__device__ __forceinline__ int imax(int a, int b) { return a > b ? a : b; }
__device__ __forceinline__ int imin(int a, int b) { return a < b ? a : b; }

// Sense-reversing grid barrier. Safe: ~219KB smem -> 1 CTA/SM, 128 CTAs <= 148 SMs,
// all co-resident in wave 1. Count self-resets -> consistent across graph replays.
__device__ __forceinline__ void grid_barrier() {
    __syncthreads();
    if (threadIdx.x == 0) {
        __threadfence();
        unsigned ph = g_phase;
        if (atomicAdd(&g_count, 1u) == (unsigned)(gridDim.x - 1)) {
            atomicExch(&g_count, 0u);
            __threadfence();
            g_phase = ph + 1u;
        } else {
            while (g_phase == ph) { __nanosleep(32); }
            __threadfence();
        }
    }
    __syncthreads();
}

__global__ void __launch_bounds__(NTHR, 1)
lstm2_kernel(const float* __restrict__ x,
             const float* __restrict__ Wih0, const float* __restrict__ bih0,
             const float* __restrict__ Whh0, const float* __restrict__ bhh0,
             const float* __restrict__ Wih1, const float* __restrict__ bih1,
             const float* __restrict__ Whh1, const float* __restrict__ bhh1,
             float* __restrict__ out)
{
    extern __shared__ char smraw[];
    ull*   w0d    = reinterpret_cast<ull*>(smraw);            // [768][16] lane-dup
    ull*   w1d    = w0d + 768 * 16;                           // [768][8]
    float* bcol   = reinterpret_cast<float*>(w1d + 768 * 8);  // [24]
    float* gates0 = bcol + 24;                                // [16][64]
    float* gates1 = gates0 + 16 * BATCH;                      // [8][64]
    float* fbase  = gates1 + 8 * BATCH;                       // 16B-aligned union
    float* vbuf   = fbase;                                    // [256][64] contiguous
    ulonglong2* red2 = reinterpret_cast<ulonglong2*>(fbase);  // [24][8][16] partial pairs

    const int tid = threadIdx.x;
    const int cta = blockIdx.x;
    const int q   = tid & 15;            // batch quad: 4q..4q+3
    const int cl  = (tid >> 4) & 1;
    const int ks  = tid >> 5;            // 0..15 == warp id
    const int ks8 = ks & 7;
    const int L0lo = 48 * ks, L0hi = L0lo + 48;
    const int k1lo = 48 * ks, k1hi = k1lo + 48;   // layer1 local k

    // ---- one-time: transpose x (B,T,K) -> g_xT (T,K,B); coalesced writes ----
    {
        const size_t total = (size_t)BATCH * T_STEPS * (DIN / 4);
        for (size_t idx = (size_t)cta * NTHR + tid; idx < total; idx += (size_t)NCTA * NTHR) {
            int b  = (int)(idx & 63);
            size_t r = idx >> 6;
            int kg = (int)(r & 63);
            int t  = (int)(r >> 6);
            float4 v4 = *reinterpret_cast<const float4*>(
                x + ((size_t)b * T_STEPS + t) * DIN + kg * 4);
            float* dst = g_xT + ((size_t)t * DIN + kg * 4) * BATCH + b;
            dst[0 * BATCH] = v4.x;
            dst[1 * BATCH] = v4.y;
            dst[2 * BATCH] = v4.z;
            dst[3 * BATCH] = v4.w;
        }
    }

    // ---- one-time: stage weights into smem (lane-duplicated for f32x2) ----
    // L0 smem col c = cl_*8 + g*2 + up -> unit u = 2*cl_+up, global j = g*512 + cta*4 + u
    for (int idx = tid; idx < 768 * 16; idx += NTHR) {
        int k = idx >> 4, c = idx & 15;
        int cl_ = c >> 3, g = (c >> 1) & 3, up = c & 1;
        int j = g * 512 + cta * 4 + 2 * cl_ + up;
        float w = (k < 256) ? Wih0[(size_t)k * 2048 + j]
                            : Whh0[(size_t)(k - 256) * 2048 + j];
        w0d[idx] = dup32(w);
    }
    // L1 smem col c = cl_*4 + g -> unit u1 = cl_, global j = g*256 + cta*2 + cl_
    for (int idx = tid; idx < 768 * 8; idx += NTHR) {
        int k = idx >> 3, c = idx & 7;
        int cl_ = c >> 2, g = c & 3;
        int j = g * 256 + cta * 2 + cl_;
        float w = (k < 512) ? Wih1[(size_t)k * 1024 + j]
                            : Whh1[(size_t)(k - 512) * 1024 + j];
        w1d[idx] = dup32(w);
    }
    if (tid < 16) {
        int cl_ = tid >> 3, g = (tid >> 1) & 3, up = tid & 1;
        int j = g * 512 + cta * 4 + 2 * cl_ + up;
        bcol[tid] = bih0[j] + bhh0[j];
    } else if (tid < 24) {
        int c = tid - 16;
        int cl_ = c >> 2, g = c & 3;
        int j = g * 256 + cta * 2 + cl_;
        bcol[tid] = bih1[j] + bhh1[j];
    }

    float cst = 0.0f;   // c0 for tid<256; c1 for tid in [256,384)

    __syncthreads();
    grid_barrier();     // g_xT complete

    // ---- main recurrence: iteration t = layer0 step t + layer1 step t-1 ----
    for (int t = 0; t <= T_STEPS; t++) {
        ull a0lo[8], a0hi[8], a1lo[4], a1hi[4];
#pragma unroll
        for (int j = 0; j < 8; j++) { a0lo[j] = 0ull; a0hi[j] = 0ull; }
#pragma unroll
        for (int j = 0; j < 4; j++) { a1lo[j] = 0ull; a1hi[j] = 0ull; }

        const bool hasL0 = (t < T_STEPS);
        const bool hasL1 = (t >= 1);

#pragma unroll 1
        for (int ci = 0; ci < 4; ci++) {
            __syncthreads();                 // union area free
            // ---- stage 256x64 chunk into vbuf, contiguous [k][b] ----
            float4* v4 = reinterpret_cast<float4*>(vbuf);
            if (ci == 0) {
                if (hasL0) {
                    const float4* src = reinterpret_cast<const float4*>(
                        g_xT + (size_t)t * DIN * BATCH);
#pragma unroll
                    for (int i = 0; i < 8; i++) v4[tid + i * NTHR] = src[tid + i * NTHR];
                }
            } else if (ci < 3) {
                if (t >= 1) {
                    const float4* src = reinterpret_cast<const float4*>(
                        g_h0[(t - 1) & 1] + (ci - 1) * 256 * BATCH);
#pragma unroll
                    for (int i = 0; i < 8; i++) v4[tid + i * NTHR] = src[tid + i * NTHR];
                } else {
#pragma unroll
                    for (int i = 0; i < 8; i++)
                        v4[tid + i * NTHR] = make_float4(0.f, 0.f, 0.f, 0.f);
                }
            } else {
                if (t >= 2) {
                    const float4* src = reinterpret_cast<const float4*>(g_h1[t & 1]);
#pragma unroll
                    for (int i = 0; i < 8; i++) v4[tid + i * NTHR] = src[tid + i * NTHR];
                } else {
#pragma unroll
                    for (int i = 0; i < 8; i++)
                        v4[tid + i * NTHR] = make_float4(0.f, 0.f, 0.f, 0.f);
                }
            }
            __syncthreads();

            const int cbase = ci << 8;
            // ---- L0 GEMM slice: 8 cols x 4 batches ----
            if (hasL0) {
                int lo = imax(L0lo, cbase), hi = imin(L0hi, cbase + 256);
                if (lo < hi) {
                    const ulonglong2* wp = reinterpret_cast<const ulonglong2*>(
                        w0d + lo * 16 + cl * 8);
                    const ulonglong2* vp = reinterpret_cast<const ulonglong2*>(
                        vbuf + (lo - cbase) * 64 + 4 * q);
#pragma unroll 2
                    for (int k = lo; k < hi; k++) {
                        ulonglong2 vv = *vp; vp += 16;           // 64 floats = 16 u2 per row
                        ulonglong2 wA = wp[0], wB = wp[1], wC = wp[2], wD = wp[3];
                        wp += 8;                                  // 16 ull per k-row
                        a0lo[0] = ffma2(wA.x, vv.x, a0lo[0]); a0hi[0] = ffma2(wA.x, vv.y, a0hi[0]);
                        a0lo[1] = ffma2(wA.y, vv.x, a0lo[1]); a0hi[1] = ffma2(wA.y, vv.y, a0hi[1]);
                        a0lo[2] = ffma2(wB.x, vv.x, a0lo[2]); a0hi[2] = ffma2(wB.x, vv.y, a0hi[2]);
                        a0lo[3] = ffma2(wB.y, vv.x, a0lo[3]); a0hi[3] = ffma2(wB.y, vv.y, a0hi[3]);
                        a0lo[4] = ffma2(wC.x, vv.x, a0lo[4]); a0hi[4] = ffma2(wC.x, vv.y, a0hi[4]);
                        a0lo[5] = ffma2(wC.y, vv.x, a0lo[5]); a0hi[5] = ffma2(wC.y, vv.y, a0hi[5]);
                        a0lo[6] = ffma2(wD.x, vv.x, a0lo[6]); a0hi[6] = ffma2(wD.x, vv.y, a0hi[6]);
                        a0lo[7] = ffma2(wD.y, vv.x, a0lo[7]); a0hi[7] = ffma2(wD.y, vv.y, a0hi[7]);
                    }
                }
            }
            // ---- L1 GEMM slice: 4 cols x 4 batches ----
            if (hasL1) {
                int lo = imax(k1lo, cbase - 256), hi = imin(k1hi, cbase);
                if (lo < hi) {
                    const ulonglong2* wp = reinterpret_cast<const ulonglong2*>(
                        w1d + lo * 8 + cl * 4);
                    const ulonglong2* vp = reinterpret_cast<const ulonglong2*>(
                        vbuf + (lo + 256 - cbase) * 64 + 4 * q);
#pragma unroll 4
                    for (int k = lo; k < hi; k++) {
                        ulonglong2 vv = *vp; vp += 16;
                        ulonglong2 wA = wp[0], wB = wp[1];
                        wp += 4;                                  // 8 ull per k1-row
                        a1lo[0] = ffma2(wA.x, vv.x, a1lo[0]); a1hi[0] = ffma2(wA.x, vv.y, a1hi[0]);
                        a1lo[1] = ffma2(wA.y, vv.x, a1lo[1]); a1hi[1] = ffma2(wA.y, vv.y, a1hi[1]);
                        a1lo[2] = ffma2(wB.x, vv.x, a1lo[2]); a1hi[2] = ffma2(wB.x, vv.y, a1hi[2]);
                        a1lo[3] = ffma2(wB.y, vv.x, a1lo[3]); a1hi[3] = ffma2(wB.y, vv.y, a1hi[3]);
                    }
                }
            }
        }

        __syncthreads();     // gemm reads done -> red2 (aliased) safe
        // ---- two-wave ks reduction: red2[c][ks8][q] ----
        if (ks < 8) {
#pragma unroll
            for (int j = 0; j < 8; j++)
                red2[(((cl << 3) + j) * 8 + ks8) * 16 + q] = make_ulonglong2(a0lo[j], a0hi[j]);
#pragma unroll
            for (int j = 0; j < 4; j++)
                red2[((16 + (cl << 2) + j) * 8 + ks8) * 16 + q] = make_ulonglong2(a1lo[j], a1hi[j]);
        }
        __syncthreads();
        if (ks >= 8) {
#pragma unroll
            for (int j = 0; j < 8; j++) {
                int idx = (((cl << 3) + j) * 8 + ks8) * 16 + q;
                ulonglong2 r = red2[idx];
                r.x = addf2(r.x, a0lo[j]); r.y = addf2(r.y, a0hi[j]);
                red2[idx] = r;
            }
#pragma unroll
            for (int j = 0; j < 4; j++) {
                int idx = ((16 + (cl << 2) + j) * 8 + ks8) * 16 + q;
                ulonglong2 r = red2[idx];
                r.x = addf2(r.x, a1lo[j]); r.y = addf2(r.y, a1hi[j]);
                red2[idx] = r;
            }
        }
        __syncthreads();

        // ---- final reduce: 24 cols x 16 quads, sum 8 partials + bias -> gates ----
        if (tid < 384) {
            int c = tid >> 4, qq = tid & 15;
            const ulonglong2* r = red2 + (c * 8) * 16 + qq;
            ull bb = dup32(bcol[c]);
            ull slo = bb, shi = bb;
#pragma unroll
            for (int s = 0; s < 8; s++) {
                ulonglong2 v = r[s * 16];
                slo = addf2(slo, v.x);
                shi = addf2(shi, v.y);
            }
            ulonglong2 res = make_ulonglong2(slo, shi);
            if (c < 16) {
                int cl_ = c >> 3, g = (c >> 1) & 3, up = c & 1;
                int u = 2 * cl_ + up;
                *reinterpret_cast<ulonglong2*>(&gates0[(g * 4 + u) * BATCH + 4 * qq]) = res;
            } else {
                int cc1 = c - 16, cl_ = cc1 >> 2, g = cc1 & 3;
                *reinterpret_cast<ulonglong2*>(&gates1[(g * 2 + cl_) * BATCH + 4 * qq]) = res;
            }
        }
        __syncthreads();

        // ---- activations (disjoint warps) ----
        if (hasL0 && tid < 256) {
            int u = tid >> 6, b = tid & 63;
            float gi = gates0[(u)      * BATCH + b];
            float gf = gates0[(4 + u)  * BATCH + b];
            float gg = gates0[(8 + u)  * BATCH + b];
            float go = gates0[(12 + u) * BATCH + b];
            cst = sigmf(gf) * cst + sigmf(gi) * tanhf(gg);
            g_h0[t & 1][(cta * 4 + u) * BATCH + b] = sigmf(go) * tanhf(cst);
        }
        if (hasL1 && tid >= 256 && tid < 384) {
            int u1 = (tid >> 6) & 1, b = tid & 63;
            float gi = gates1[(u1)     * BATCH + b];
            float gf = gates1[(2 + u1) * BATCH + b];
            float gg = gates1[(4 + u1) * BATCH + b];
            float go = gates1[(6 + u1) * BATCH + b];
            cst = sigmf(gf) * cst + sigmf(gi) * tanhf(gg);
            float h = sigmf(go) * tanhf(cst);
            int s = t - 1;
            g_h1[s & 1][(cta * 2 + u1) * BATCH + b] = h;
            out[((size_t)b * T_STEPS + s) * H1 + cta * 2 + u1] = h;
        }

        if (t < T_STEPS) grid_barrier();
    }
}

// smem: weights 147456 + bcol 96 + gates 6144 + union max(vbuf 65536, red 49152)
#define SMEM_BYTES (147456 + 96 + 6144 + 65536)

extern "C" void kernel_launch(void* const* d_in, const int* in_sizes, int n_in,
                              void* d_out, int out_size) {
    (void)in_sizes; (void)n_in; (void)out_size;
    cudaFuncSetAttribute(lstm2_kernel,
                         cudaFuncAttributeMaxDynamicSharedMemorySize, SMEM_BYTES);
    lstm2_kernel<<<NCTA, NTHR, SMEM_BYTES>>>(
        (const float*)d_in[0],
        (const float*)d_in[1], (const float*)d_in[2],
        (const float*)d_in[3], (const float*)d_in[4],
        (const float*)d_in[5], (const float*)d_in[6],
        (const float*)d_in[7], (const float*)d_in[8],
        (float*)d_out);
}